// round 1
// baseline (speedup 1.0000x reference)
#include <cuda_runtime.h>
#include <cstdint>

#define N_NODES 100000
#define N_EDGES 1600000
#define IN_CH   128
#define HID     64
#define NG      256
#define OUTC    10

// ---------------- scratch (device globals; no allocation) ----------------
__device__ int   g_is64;
__device__ int   g_deg[N_NODES];
__device__ float g_dinv[N_NODES];
__device__ float g_hs [(size_t)N_NODES * HID];   // (x@W)*dinv[node]
__device__ float g_acc[(size_t)N_NODES * HID];   // running aggregation (init = self-loop hs)
__device__ float g_pool[NG * HID];
__device__ float g_cnt [NG];

// index loader handling int64-vs-int32 edge/batch buffers
__device__ __forceinline__ int load_idx(const void* p, long long i, int is64) {
    if (is64) return (int)((const long long*)p)[i];
    return ((const int*)p)[i];
}

// ---------------- dtype sniff: int64 => odd 32-bit words are 0 ----------------
__global__ void k_detect(const unsigned* __restrict__ e) {
    if (blockIdx.x == 0 && threadIdx.x == 0) {
        int z = 1;
        for (int i = 0; i < 64; i++) {
            if (e[2 * i + 1] != 0u) { z = 0; break; }
        }
        g_is64 = z;
    }
}

// ---------------- init: deg=1 (self loop), zero pooling buffers ----------------
__global__ void k_init() {
    int i = blockIdx.x * blockDim.x + threadIdx.x;
    if (i < N_NODES) g_deg[i] = 1;
    if (i < NG * HID) g_pool[i] = 0.f;
    if (i < NG) g_cnt[i] = 0.f;
}

// ---------------- in-degree count over dst ----------------
__global__ void k_degcount(const void* __restrict__ ei) {
    int i = blockIdx.x * blockDim.x + threadIdx.x;
    if (i < N_EDGES) {
        int d = load_idx(ei, (long long)N_EDGES + i, g_is64);
        atomicAdd(&g_deg[d], 1);
    }
}

__global__ void k_dinv() {
    int i = blockIdx.x * blockDim.x + threadIdx.x;
    if (i < N_NODES) g_dinv[i] = rsqrtf((float)g_deg[i]);
}

// ---------------- GEMM: hs = (x @ W) * dinv ; acc = hs (self-loop term) -------
// 256 threads/block, 32 rows/block (100000/32 = 3125 exact), two K-phases of 64.
__global__ __launch_bounds__(256) void k_gemm(const float* __restrict__ x,
                                              const float* __restrict__ W) {
    __shared__ __align__(16) float Ws[64 * 64];      // [k][c] for this phase
    __shared__ __align__(16) float xs[32 * 68];      // padded stride 68 (bank-safe)

    const int t    = threadIdx.x;
    const int row0 = blockIdx.x * 32;
    const int r    = t >> 3;           // 0..31
    const int c0   = (t & 7) * 8;      // 0,8,...,56

    float acc[8];
#pragma unroll
    for (int j = 0; j < 8; j++) acc[j] = 0.f;

    for (int ph = 0; ph < 2; ph++) {
        __syncthreads();
        // load W k-slab: 64x64 floats = 1024 float4
#pragma unroll
        for (int i = t; i < 1024; i += 256) {
            ((float4*)Ws)[i] = ((const float4*)(W + ph * 64 * 64))[i];
        }
        // load x tile: 32 rows x 64 cols = 512 float4
#pragma unroll
        for (int i = t; i < 512; i += 256) {
            int rr = i >> 4, c4 = i & 15;
            float4 v = ((const float4*)(x + (size_t)(row0 + rr) * IN_CH + ph * 64))[c4];
            *(float4*)(xs + rr * 68 + c4 * 4) = v;
        }
        __syncthreads();

#pragma unroll
        for (int k = 0; k < 64; k++) {
            float  xv = xs[r * 68 + k];
            float4 w0 = *(const float4*)(Ws + k * 64 + c0);
            float4 w1 = *(const float4*)(Ws + k * 64 + c0 + 4);
            acc[0] = fmaf(xv, w0.x, acc[0]);
            acc[1] = fmaf(xv, w0.y, acc[1]);
            acc[2] = fmaf(xv, w0.z, acc[2]);
            acc[3] = fmaf(xv, w0.w, acc[3]);
            acc[4] = fmaf(xv, w1.x, acc[4]);
            acc[5] = fmaf(xv, w1.y, acc[5]);
            acc[6] = fmaf(xv, w1.z, acc[6]);
            acc[7] = fmaf(xv, w1.w, acc[7]);
        }
    }

    const int   row = row0 + r;
    const float dv  = g_dinv[row];
    float4 o0 = make_float4(acc[0] * dv, acc[1] * dv, acc[2] * dv, acc[3] * dv);
    float4 o1 = make_float4(acc[4] * dv, acc[5] * dv, acc[6] * dv, acc[7] * dv);
    float4* hp = (float4*)(g_hs  + (size_t)row * HID + c0);
    float4* ap = (float4*)(g_acc + (size_t)row * HID + c0);
    hp[0] = o0; hp[1] = o1;
    ap[0] = o0; ap[1] = o1;
}

// ---------------- edge scatter: acc[dst] += hs[src], vectorized red.v4 -------
// 16 lanes per edge (16 x float4 = 64 floats), 2 edges per warp.
// grid: E/2 warps = 800000 warps -> 100000 blocks x 256 threads, exact.
__global__ __launch_bounds__(256) void k_scatter(const void* __restrict__ ei) {
    const int gt   = blockIdx.x * blockDim.x + threadIdx.x;
    const int warp = gt >> 5;
    const int lane = gt & 31;
    const long long e = (long long)warp * 2 + (lane >> 4);
    const int sub  = lane & 15;
    const int is64 = g_is64;

    const int s = load_idx(ei, e, is64);
    const int d = load_idx(ei, (long long)N_EDGES + e, is64);

    float4 v = ((const float4*)(g_hs + (size_t)s * HID))[sub];
    float* dp = g_acc + (size_t)d * HID + sub * 4;
    asm volatile("red.global.add.v4.f32 [%0], {%1, %2, %3, %4};"
                 :: "l"(dp), "f"(v.x), "f"(v.y), "f"(v.z), "f"(v.w)
                 : "memory");
}

// ---------------- epilogue: hidden = relu(dinv*acc + b); pool by graph -------
// thread = (node, 4-channel chunk); N*16 = 1.6M threads, 6250 blocks exact.
__global__ __launch_bounds__(256) void k_epi(const void* __restrict__ batch,
                                             const float* __restrict__ bconv) {
    const int gt   = blockIdx.x * blockDim.x + threadIdx.x;
    const int node = gt >> 4;
    const int q    = gt & 15;

    const float dv = g_dinv[node];
    float4 a = ((const float4*)(g_acc + (size_t)node * HID))[q];
    float4 b = ((const float4*)bconv)[q];
    float4 h;
    h.x = fmaxf(fmaf(dv, a.x, b.x), 0.f);
    h.y = fmaxf(fmaf(dv, a.y, b.y), 0.f);
    h.z = fmaxf(fmaf(dv, a.z, b.z), 0.f);
    h.w = fmaxf(fmaf(dv, a.w, b.w), 0.f);

    const int g = load_idx(batch, node, g_is64);
    float* pp = g_pool + g * HID + q * 4;
    asm volatile("red.global.add.v4.f32 [%0], {%1, %2, %3, %4};"
                 :: "l"(pp), "f"(h.x), "f"(h.y), "f"(h.z), "f"(h.w)
                 : "memory");
    if (q == 0) atomicAdd(&g_cnt[g], 1.0f);
}

// ---------------- final: out = (pool/cnt) @ W_lin + b_lin ----------------
__global__ __launch_bounds__(256) void k_final(const float* __restrict__ Wl,
                                               const float* __restrict__ bl,
                                               float* __restrict__ out) {
    __shared__ float sW[HID * OUTC];
    __shared__ float sb[OUTC];
    const int t = threadIdx.x;
    for (int i = t; i < HID * OUTC; i += 256) sW[i] = Wl[i];
    if (t < OUTC) sb[t] = bl[t];
    __syncthreads();

    // thread t == graph index
    const float inv = 1.f / fmaxf(g_cnt[t], 1.f);
    float acc[OUTC];
#pragma unroll
    for (int j = 0; j < OUTC; j++) acc[j] = sb[j];
#pragma unroll 4
    for (int c = 0; c < HID; c++) {
        float p = g_pool[t * HID + c] * inv;
#pragma unroll
        for (int j = 0; j < OUTC; j++) acc[j] = fmaf(p, sW[c * OUTC + j], acc[j]);
    }
#pragma unroll
    for (int j = 0; j < OUTC; j++) out[t * OUTC + j] = acc[j];
}

// ---------------- launch ----------------
extern "C" void kernel_launch(void* const* d_in, const int* in_sizes, int n_in,
                              void* d_out, int out_size) {
    const float* x     = (const float*)d_in[0];
    const void*  ei    = d_in[1];
    const void*  batch = d_in[2];
    const float* Wc    = (const float*)d_in[3];
    const float* bc    = (const float*)d_in[4];
    const float* Wl    = (const float*)d_in[5];
    const float* bl    = (const float*)d_in[6];
    float*       out   = (float*)d_out;

    k_detect  <<<1, 32>>>((const unsigned*)ei);
    k_init    <<<(N_NODES + 255) / 256, 256>>>();
    k_degcount<<<(N_EDGES + 255) / 256, 256>>>(ei);
    k_dinv    <<<(N_NODES + 255) / 256, 256>>>();
    k_gemm    <<<N_NODES / 32, 256>>>(x, Wc);
    k_scatter <<<(N_EDGES / 2 * 32) / 256, 256>>>(ei);
    k_epi     <<<(N_NODES * 16) / 256, 256>>>(batch, bc);
    k_final   <<<1, 256>>>(Wl, bl, out);
}